// round 3
// baseline (speedup 1.0000x reference)
#include <cuda_runtime.h>
#include <cuda_bf16.h>

#define BATCH     8192
#define IN_CAP_SZ 5
#define IN_CAP_N  1152
#define OUT_CAP_N 55
#define F4_PER_K  288    // 1152/4 float4 per (b,i) row
#define F4_PER_B  1440   // 5*288 float4 per batch element

__global__ __launch_bounds__(128, 6) void digitcaps_kernel(
    const float4* __restrict__ u4,   // (B, 5, 1152) as float4
    const float4* __restrict__ w4,   // (1152,) as float4
    const float*  __restrict__ bvec, // (55,)
    float*        __restrict__ out)  // (B, 55)
{
    __shared__ float4 ws[F4_PER_K];
    const int tid = threadIdx.x;
    for (int idx = tid; idx < F4_PER_K; idx += 128)
        ws[idx] = w4[idx];
    __syncthreads();

    const int lane = tid & 31;
    const int warp = tid >> 5;
    const int bb   = (blockIdx.x * 4 + warp) * 2;   // grid=1024, 4 warps, 2 elems/warp

    const float4* upA = u4 + (size_t)bb * F4_PER_B + lane;
    const float4* upB = upA + F4_PER_B;

    // ---- Phase 1: 10 independent load+FMA streams (2 elems x 5 capsules) ----
    float acc[2][5];
    #pragma unroll
    for (int e = 0; e < 2; e++)
        #pragma unroll
        for (int i = 0; i < 5; i++) acc[e][i] = 0.f;

    #pragma unroll
    for (int j = 0; j < 9; j++) {
        const float4 w = ws[j * 32 + lane];
        #pragma unroll
        for (int i = 0; i < 5; i++) {
            const float4 xa = __ldcs(&upA[i * F4_PER_K + j * 32]);
            const float4 xb = __ldcs(&upB[i * F4_PER_K + j * 32]);
            acc[0][i] = fmaf(xa.x, w.x, fmaf(xa.y, w.y, fmaf(xa.z, w.z, fmaf(xa.w, w.w, acc[0][i]))));
            acc[1][i] = fmaf(xb.x, w.x, fmaf(xb.y, w.y, fmaf(xb.z, w.z, fmaf(xb.w, w.w, acc[1][i]))));
        }
    }

    // 10 interleaved butterfly reductions -> all lanes hold uh[e][i]
    #pragma unroll
    for (int off = 16; off > 0; off >>= 1) {
        #pragma unroll
        for (int e = 0; e < 2; e++)
            #pragma unroll
            for (int i = 0; i < 5; i++)
                acc[e][i] += __shfl_xor_sync(0xffffffffu, acc[e][i], off);
    }

    // ---- Phase 2: routing. Lane owns out-capsules o0=lane, o1=lane+32. ----
    const int  o0   = lane;
    const int  o1   = lane + 32;
    const bool has1 = (o1 < OUT_CAP_N);

    const float base0 = bvec[o0];
    const float base1 = has1 ? bvec[o1] : 0.f;

    // Iteration 0: softmax depends ONLY on bvec -> one reduction pair per warp,
    // shared by both batch elements.
    float m = has1 ? fmaxf(base0, base1) : base0;
    #pragma unroll
    for (int off = 16; off > 0; off >>= 1)
        m = fmaxf(m, __shfl_xor_sync(0xffffffffu, m, off));

    const float e0 = __expf(base0 - m);
    const float e1 = has1 ? __expf(base1 - m) : 0.f;
    float d = e0 + e1;
    #pragma unroll
    for (int off = 16; off > 0; off >>= 1)
        d += __shfl_xor_sync(0xffffffffu, d, off);

    float v0[2], v1[2];
    #pragma unroll
    for (int e = 0; e < 2; e++) {
        const float sumUh = acc[e][0] + acc[e][1] + acc[e][2] + acc[e][3] + acc[e][4];
        const float r  = __fdividef(sumUh, d);
        const float s0 = e0 * r;
        const float s1 = e1 * r;
        v0[e] = __fdividef(fabsf(s0) * s0, 1.f + s0 * s0);   // squash, OUT_CAP_SZ=1
        v1[e] = __fdividef(fabsf(s1) * s1, 1.f + s1 * s1);
    }

    // Iteration 1 (final): b_ij(o,i) = base_o + v_o*uh_i. 10 interleaved softmaxes.
    float mi[2][5];
    #pragma unroll
    for (int e = 0; e < 2; e++)
        #pragma unroll
        for (int i = 0; i < 5; i++) {
            mi[e][i] = fmaf(v0[e], acc[e][i], base0);
            if (has1) mi[e][i] = fmaxf(mi[e][i], fmaf(v1[e], acc[e][i], base1));
        }
    #pragma unroll
    for (int off = 16; off > 0; off >>= 1)
        #pragma unroll
        for (int e = 0; e < 2; e++)
            #pragma unroll
            for (int i = 0; i < 5; i++)
                mi[e][i] = fmaxf(mi[e][i], __shfl_xor_sync(0xffffffffu, mi[e][i], off));

    float e0i[2][5], e1i[2][5], di[2][5];
    #pragma unroll
    for (int e = 0; e < 2; e++)
        #pragma unroll
        for (int i = 0; i < 5; i++) {
            e0i[e][i] = __expf(fmaf(v0[e], acc[e][i], base0) - mi[e][i]);
            e1i[e][i] = has1 ? __expf(fmaf(v1[e], acc[e][i], base1) - mi[e][i]) : 0.f;
            di[e][i]  = e0i[e][i] + e1i[e][i];
        }
    #pragma unroll
    for (int off = 16; off > 0; off >>= 1)
        #pragma unroll
        for (int e = 0; e < 2; e++)
            #pragma unroll
            for (int i = 0; i < 5; i++)
                di[e][i] += __shfl_xor_sync(0xffffffffu, di[e][i], off);

    #pragma unroll
    for (int e = 0; e < 2; e++) {
        float t0 = 0.f, t1 = 0.f;
        #pragma unroll
        for (int i = 0; i < 5; i++) {
            const float r = __fdividef(acc[e][i], di[e][i]);
            t0 = fmaf(e0i[e][i], r, t0);
            t1 = fmaf(e1i[e][i], r, t1);
        }
        const float w0 = __fdividef(fabsf(t0) * t0, 1.f + t0 * t0);
        const float w1 = __fdividef(fabsf(t1) * t1, 1.f + t1 * t1);

        out[(size_t)(bb + e) * OUT_CAP_N + o0] = w0;
        if (has1) out[(size_t)(bb + e) * OUT_CAP_N + o1] = w1;
    }
}

extern "C" void kernel_launch(void* const* d_in, const int* in_sizes, int n_in,
                              void* d_out, int out_size) {
    const float4* u4   = (const float4*)d_in[0];  // (8192,5,128,3,3) f32
    const float4* w4   = (const float4*)d_in[1];  // (1,1152,1) f32
    const float*  bvec = (const float*) d_in[2];  // (55,1) f32
    float*        out  = (float*)d_out;           // (8192,55,1) f32

    digitcaps_kernel<<<BATCH / 8, 128>>>(u4, w4, bvec, out);
}